// round 3
// baseline (speedup 1.0000x reference)
#include <cuda_runtime.h>
#include <cuda_bf16.h>

// Fixed shapes for this problem.
#define NIMG 8
#define NC   19
#define HH   512
#define WW   512
#define HW   (HH * WW)        // 262144
#define PIX  (NIMG * HW)      // 2097152
#define PIX4 (PIX / 4)        // 524288
#define NBLK1 2048            // PIX4 / 256
#define GRID2 296             // slow-path grids (~2 waves)

#define OHEM_THRESH 0.7f

// ---------------- scratch (device globals; no allocation allowed) ----------
__device__ float        g_prob[PIX];       // prob of target class; 4.0f sentinel for ignored
__device__ int          g_pnv[NBLK1];      // per-block valid counts
__device__ int          g_pcl[NBLK1];      // per-block count(prob<0.7)
__device__ float        g_psl[NBLK1];      // per-block sum loss(prob<0.7)
__device__ unsigned     g_hist16[65536];   // slow path: top-16-bit histogram
__device__ unsigned     g_cand[PIX];       // slow path: candidate keys in selected bin
__device__ unsigned     g_cand_cnt;
__device__ float        g_rsl[512];        // slow-path reduce partials
__device__ int          g_rcl[512];
__device__ unsigned     g_c1, g_c2, g_c3, g_c4;  // last-block tickets (self-resetting)
__device__ int          g_done;            // 1 => fast path, out already written
__device__ int          g_krem;            // remaining rank
__device__ unsigned     g_selbin;          // selected 16-bit bin
__device__ float        g_threshold;

// ======================= K1: fused compute + decide ========================
__global__ void __launch_bounds__(256) k_compute(const float* __restrict__ pred,
                                                 const int* __restrict__ tgt,
                                                 const int* __restrict__ min_kept,
                                                 float* __restrict__ out) {
    int tid = blockIdx.x * 256 + threadIdx.x;   // 0..PIX4-1
    int p0  = tid * 4;
    int n   = p0 >> 18;                         // / HW
    int hw  = p0 & (HW - 1);
    const float* base = pred + (size_t)(n * NC) * HW + hw;

    int4 t4 = *(const int4*)(tgt + p0);
    int tc0 = max(t4.x, 0), tc1 = max(t4.y, 0), tc2 = max(t4.z, 0), tc3 = max(t4.w, 0);

    // Streaming sum-of-exp (logits are bounded; no max subtraction needed).
    float s0 = 0.f, s1 = 0.f, s2 = 0.f, s3 = 0.f;
    float xt0 = 0.f, xt1 = 0.f, xt2 = 0.f, xt3 = 0.f;
#pragma unroll
    for (int c = 0; c < NC; c++) {
        float4 v = *(const float4*)(base + (size_t)c * HW);
        s0 += __expf(v.x); s1 += __expf(v.y);
        s2 += __expf(v.z); s3 += __expf(v.w);
        if (c == tc0) xt0 = v.x;
        if (c == tc1) xt1 = v.y;
        if (c == tc2) xt2 = v.z;
        if (c == tc3) xt3 = v.w;
    }

    float lp[4] = { xt0 - __logf(s0), xt1 - __logf(s1),
                    xt2 - __logf(s2), xt3 - __logf(s3) };
    int   tg[4] = { t4.x, t4.y, t4.z, t4.w };
    float pr[4];
    int cv = 0, cl = 0; float sl = 0.f;
#pragma unroll
    for (int j = 0; j < 4; j++) {
        float p = __expf(lp[j]);
        bool valid = (tg[j] != -1);
        pr[j] = valid ? p : 4.0f;               // sentinel: never selected
        cv += valid;
        bool sel = valid && (p < OHEM_THRESH);
        cl += sel;
        if (sel) sl += (-lp[j]);
    }
    *(float4*)&g_prob[p0] = make_float4(pr[0], pr[1], pr[2], pr[3]);

    // block reduce of speculative fast-path stats
#pragma unroll
    for (int o = 16; o; o >>= 1) {
        cv += __shfl_down_sync(0xFFFFFFFFu, cv, o);
        cl += __shfl_down_sync(0xFFFFFFFFu, cl, o);
        sl += __shfl_down_sync(0xFFFFFFFFu, sl, o);
    }
    __shared__ int scv[8], scl[8];
    __shared__ float ssl[8];
    int w = threadIdx.x >> 5, l = threadIdx.x & 31;
    if (l == 0) { scv[w] = cv; scl[w] = cl; ssl[w] = sl; }
    __syncthreads();
    if (threadIdx.x == 0) {
        int a1 = 0, a2 = 0; float a3 = 0.f;
#pragma unroll
        for (int i = 0; i < 8; i++) { a1 += scv[i]; a2 += scl[i]; a3 += ssl[i]; }
        g_pnv[blockIdx.x] = a1;
        g_pcl[blockIdx.x] = a2;
        g_psl[blockIdx.x] = a3;
    }

    // ---- last finished block performs the decide stage ----
    __shared__ int s_last;
    __threadfence();
    if (threadIdx.x == 0)
        s_last = (atomicAdd(&g_c1, 1u) == (unsigned)(gridDim.x - 1));
    __syncthreads();
    if (!s_last) return;

    int t = threadIdx.x;
    long long anv = 0, acl = 0; double asl = 0.0;
    for (int i = t; i < NBLK1; i += 256) {        // fixed per-thread assignment
        anv += g_pnv[i]; acl += g_pcl[i]; asl += (double)g_psl[i];
    }
    __shared__ long long rnv[256], rcl2[256];
    __shared__ double rsl2[256];
    rnv[t] = anv; rcl2[t] = acl; rsl2[t] = asl;
    __syncthreads();
#pragma unroll
    for (int o = 128; o; o >>= 1) {
        if (t < o) { rnv[t] += rnv[t + o]; rcl2[t] += rcl2[t + o]; rsl2[t] += rsl2[t + o]; }
        __syncthreads();
    }
    __shared__ int sdone;
    if (t == 0) {
        g_c1 = 0;
        long long nv = rnv[0], cl2 = rcl2[0];
        double sum = rsl2[0];
        if (nv == 0) {
            out[0] = 0.0f; g_done = 1; sdone = 1;
        } else {
            long long k = (long long)min_kept[0];
            if (k > nv - 1) k = nv - 1;
            if (k < 0) k = 0;
            if (cl2 > k) {   // kth smallest prob < 0.7 -> threshold == 0.7; done.
                double c = (double)cl2; if (c < 1.0) c = 1.0;
                out[0] = (float)(sum / c);
                g_done = 1; sdone = 1;
            } else {
                g_done = 0; g_krem = (int)k; g_cand_cnt = 0u; sdone = 0;
            }
        }
    }
    __syncthreads();
    if (!sdone) {   // prepare slow path: zero the 16-bit histogram
        for (int i = t; i < 65536; i += 256) g_hist16[i] = 0u;
    }
}

// ============ K2 (slow path): 16-bit histogram + bin select ================
__global__ void __launch_bounds__(256) k_hist() {
    if (g_done) { // still must tick the counter? No: counter only used on slow path.
        return;
    }
    for (int i = blockIdx.x * blockDim.x + threadIdx.x; i < PIX;
         i += gridDim.x * blockDim.x) {
        unsigned key = __float_as_uint(g_prob[i]);
        if (key < 0x40000000u)                   // valid probs (<2.0); sentinel 4.0 excluded
            atomicAdd(&g_hist16[key >> 16], 1u);
    }
    __threadfence();
    __shared__ int s_last;
    if (threadIdx.x == 0)
        s_last = (atomicAdd(&g_c2, 1u) == (unsigned)(gridDim.x - 1));
    __syncthreads();
    if (!s_last) return;

    int t = threadIdx.x;
    unsigned k = (unsigned)g_krem;               // read before any write
    unsigned tot = 0;
    for (int j = 0; j < 256; j++) tot += g_hist16[t * 256 + j];
    __shared__ unsigned ps[256];
    ps[t] = tot; __syncthreads();
    for (int o = 1; o < 256; o <<= 1) {
        unsigned v = (t >= o) ? ps[t - o] : 0u;
        __syncthreads();
        ps[t] += v;
        __syncthreads();
    }
    unsigned excl = ps[t] - tot;                 // exclusive prefix of this thread's range
    if (k >= excl && k < excl + tot) {
        unsigned run = excl;
        for (int j = 0; j < 256; j++) {
            unsigned c = g_hist16[t * 256 + j];
            if (k < run + c) { g_selbin = (unsigned)(t * 256 + j); g_krem = (int)(k - run); break; }
            run += c;
        }
    }
    if (t == 0) g_c2 = 0;
}

// ======== K3 (slow path): gather candidates + exact low-16-bit select ======
__global__ void __launch_bounds__(256) k_gather() {
    if (g_done) return;
    unsigned sb = g_selbin;
    for (int i = blockIdx.x * blockDim.x + threadIdx.x; i < PIX;
         i += gridDim.x * blockDim.x) {
        unsigned key = __float_as_uint(g_prob[i]);
        if ((key >> 16) == sb) {
            unsigned pos = atomicAdd(&g_cand_cnt, 1u);
            g_cand[pos] = key;
        }
    }
    __threadfence();
    __shared__ int s_last;
    if (threadIdx.x == 0)
        s_last = (atomicAdd(&g_c3, 1u) == (unsigned)(gridDim.x - 1));
    __syncthreads();
    if (!s_last) return;

    int t = threadIdx.x;
    unsigned nc = g_cand_cnt;
    __shared__ unsigned sh[256];
    __shared__ unsigned sb1, skk;
    // round 1: byte1 (bits 15:8)
    sh[t] = 0; __syncthreads();
    for (unsigned i = t; i < nc; i += 256)
        atomicAdd(&sh[(g_cand[i] >> 8) & 0xFFu], 1u);
    __syncthreads();
    if (t == 0) {
        unsigned k = (unsigned)g_krem, run = 0;
        for (int j = 0; j < 256; j++) {
            unsigned c = sh[j];
            if (k < run + c) { sb1 = (unsigned)j; skk = k - run; break; }
            run += c;
        }
    }
    __syncthreads();
    unsigned b1 = sb1;
    // round 2: byte0 among byte1 == b1
    sh[t] = 0; __syncthreads();
    for (unsigned i = t; i < nc; i += 256) {
        unsigned key = g_cand[i];
        if (((key >> 8) & 0xFFu) == b1) atomicAdd(&sh[key & 0xFFu], 1u);
    }
    __syncthreads();
    if (t == 0) {
        unsigned k = skk, run = 0, b0 = 0;
        for (int j = 0; j < 256; j++) {
            unsigned c = sh[j];
            if (k < run + c) { b0 = (unsigned)j; break; }
            run += c;
        }
        unsigned key = (g_selbin << 16) | (b1 << 8) | b0;
        g_threshold = fmaxf(__uint_as_float(key), OHEM_THRESH);
        g_c3 = 0;
    }
}

// ============== K4 (slow path): masked mean over hard examples =============
__global__ void __launch_bounds__(256) k_reduce(float* __restrict__ out) {
    if (g_done) return;
    float th = g_threshold;
    float sl = 0.f; int cl = 0;
    for (int i = blockIdx.x * blockDim.x + threadIdx.x; i < PIX;
         i += gridDim.x * blockDim.x) {
        float p = g_prob[i];                     // sentinel 4.0 never < th (th in (0.7,1))
        if (p < th) { sl += -__logf(fmaxf(p, 1e-38f)); cl++; }
    }
#pragma unroll
    for (int o = 16; o; o >>= 1) {
        sl += __shfl_down_sync(0xFFFFFFFFu, sl, o);
        cl += __shfl_down_sync(0xFFFFFFFFu, cl, o);
    }
    __shared__ float ssl[8];
    __shared__ int   scl[8];
    int w = threadIdx.x >> 5, l = threadIdx.x & 31;
    if (l == 0) { ssl[w] = sl; scl[w] = cl; }
    __syncthreads();
    if (threadIdx.x == 0) {
        float a3 = 0.f; int a2 = 0;
#pragma unroll
        for (int i = 0; i < 8; i++) { a3 += ssl[i]; a2 += scl[i]; }
        g_rsl[blockIdx.x] = a3;
        g_rcl[blockIdx.x] = a2;
    }
    __threadfence();
    __shared__ int s_last;
    if (threadIdx.x == 0)
        s_last = (atomicAdd(&g_c4, 1u) == (unsigned)(gridDim.x - 1));
    __syncthreads();
    if (!s_last) return;

    int t = threadIdx.x;
    double asl = 0.0; long long acl = 0;
    for (int i = t; i < (int)gridDim.x; i += 256) { asl += (double)g_rsl[i]; acl += g_rcl[i]; }
    __shared__ double rs[256];
    __shared__ long long rc[256];
    rs[t] = asl; rc[t] = acl;
    __syncthreads();
#pragma unroll
    for (int o = 128; o; o >>= 1) {
        if (t < o) { rs[t] += rs[t + o]; rc[t] += rc[t + o]; }
        __syncthreads();
    }
    if (t == 0) {
        double c = (double)rc[0]; if (c < 1.0) c = 1.0;
        out[0] = (float)(rs[0] / c);
        g_c4 = 0;
    }
}

// ---------------------------------------------------------------------------
extern "C" void kernel_launch(void* const* d_in, const int* in_sizes, int n_in,
                              void* d_out, int out_size) {
    const float* pred = (const float*)d_in[0];
    const int*   tgt  = (const int*)d_in[1];
    const int*   mk   = (const int*)d_in[2];
    float* out = (float*)d_out;

    k_compute<<<NBLK1, 256>>>(pred, tgt, mk, out);   // fused compute + decide
    k_hist<<<GRID2, 256>>>();                        // slow path only (early exit)
    k_gather<<<GRID2, 256>>>();                      // slow path only
    k_reduce<<<GRID2, 256>>>(out);                   // slow path only
}

// round 5
// speedup vs baseline: 1.2880x; 1.2880x over previous
#include <cuda_runtime.h>
#include <cuda_bf16.h>

// Fixed shapes for this problem.
#define NIMG 8
#define NC   19
#define HW   (512 * 512)      // 262144
#define PIX  (NIMG * HW)      // 2097152
#define PIX4 (PIX / 4)        // 524288
#define GRID 296              // persistent grid: 2 CTAs/SM x 148 SMs (co-resident)
#define NTHR 256

#define OHEM_THRESH 0.7f

// ---------------- scratch (device globals; no allocation allowed) ----------
__device__ float        g_prob[PIX];       // slow path only
__device__ int          g_pnv[GRID];       // per-block valid counts
__device__ int          g_pcl[GRID];       // per-block count(prob<0.7)
__device__ float        g_psl[GRID];       // per-block sum loss(prob<0.7)
__device__ unsigned     g_hist16[65536];   // slow path: top-16-bit histogram
__device__ unsigned     g_cand[PIX];       // slow path: candidate keys in selected bin
__device__ unsigned     g_cand_cnt;
__device__ float        g_rsl[GRID];       // slow-path reduce partials
__device__ int          g_rcl[GRID];
__device__ unsigned     g_c4;              // last-block ticket (self-resetting)
__device__ int          g_done;            // 1 => fast path complete
__device__ int          g_krem;            // remaining rank
__device__ unsigned     g_selbin;          // selected 16-bit bin
__device__ unsigned     g_krem2;           // rank within selected bin
__device__ float        g_threshold;
// software global barrier (generation-based; monotone across graph replays)
__device__ unsigned     g_bar_cnt;
__device__ unsigned     g_bar_gen;

__device__ __forceinline__ void gbar() {
    __syncthreads();
    __threadfence();
    if (threadIdx.x == 0) {
        unsigned gen = *(volatile unsigned*)&g_bar_gen;
        if (atomicAdd(&g_bar_cnt, 1u) == GRID - 1) {
            g_bar_cnt = 0;
            __threadfence();
            atomicExch(&g_bar_gen, gen + 1);
        } else {
            while (*(volatile unsigned*)&g_bar_gen == gen) { __nanosleep(32); }
        }
    }
    __syncthreads();
    __threadfence();
}

// Per-pixel-group compute: returns 4 probs (sentinel 4.0 for ignored) and 4 log-probs.
__device__ __forceinline__ void compute4(const float* __restrict__ pred,
                                         const int* __restrict__ tgt,
                                         int tid, float pr[4], float lp[4], int tg[4]) {
    int p0 = tid * 4;
    int n  = p0 >> 18;
    int hw = p0 & (HW - 1);
    const float* base = pred + (size_t)(n * NC) * HW + hw;
    int4 t4 = *(const int4*)(tgt + p0);
    int tc0 = max(t4.x, 0), tc1 = max(t4.y, 0), tc2 = max(t4.z, 0), tc3 = max(t4.w, 0);

    float s0 = 0.f, s1 = 0.f, s2 = 0.f, s3 = 0.f;
    float xt0 = 0.f, xt1 = 0.f, xt2 = 0.f, xt3 = 0.f;
#pragma unroll
    for (int c = 0; c < NC; c++) {
        float4 v = __ldcs((const float4*)(base + (size_t)c * HW));
        s0 += __expf(v.x); s1 += __expf(v.y);
        s2 += __expf(v.z); s3 += __expf(v.w);
        if (c == tc0) xt0 = v.x;
        if (c == tc1) xt1 = v.y;
        if (c == tc2) xt2 = v.z;
        if (c == tc3) xt3 = v.w;
    }
    lp[0] = xt0 - __logf(s0); lp[1] = xt1 - __logf(s1);
    lp[2] = xt2 - __logf(s2); lp[3] = xt3 - __logf(s3);
    tg[0] = t4.x; tg[1] = t4.y; tg[2] = t4.z; tg[3] = t4.w;
#pragma unroll
    for (int j = 0; j < 4; j++) {
        float p = __expf(lp[j]);
        pr[j] = (tg[j] != -1) ? p : 4.0f;
    }
}

// =================== single persistent cooperative kernel ==================
__global__ void __launch_bounds__(NTHR, 2) k_ohem(const float* __restrict__ pred,
                                                  const int* __restrict__ tgt,
                                                  const int* __restrict__ min_kept,
                                                  float* __restrict__ out) {
    const int t = threadIdx.x;
    const int bid = blockIdx.x;

    // ---- phase 0: stream compute + speculative fast-path stats (no g_prob) ----
    int cv = 0, cl = 0; float sl = 0.f;
    for (int tid = bid * NTHR + t; tid < PIX4; tid += GRID * NTHR) {
        float pr[4], lp[4]; int tg[4];
        compute4(pred, tgt, tid, pr, lp, tg);
#pragma unroll
        for (int j = 0; j < 4; j++) {
            bool valid = (tg[j] != -1);
            cv += valid;
            bool sel = valid && (pr[j] < OHEM_THRESH);
            cl += sel;
            if (sel) sl += (-lp[j]);
        }
    }
#pragma unroll
    for (int o = 16; o; o >>= 1) {
        cv += __shfl_down_sync(0xFFFFFFFFu, cv, o);
        cl += __shfl_down_sync(0xFFFFFFFFu, cl, o);
        sl += __shfl_down_sync(0xFFFFFFFFu, sl, o);
    }
    __shared__ int scv[8], scl[8];
    __shared__ float ssl[8];
    {
        int w = t >> 5, l = t & 31;
        if (l == 0) { scv[w] = cv; scl[w] = cl; ssl[w] = sl; }
        __syncthreads();
        if (t == 0) {
            int a1 = 0, a2 = 0; float a3 = 0.f;
#pragma unroll
            for (int i = 0; i < 8; i++) { a1 += scv[i]; a2 += scl[i]; a3 += ssl[i]; }
            g_pnv[bid] = a1; g_pcl[bid] = a2; g_psl[bid] = a3;
        }
    }
    gbar();

    // ---- phase 1: block 0 reduces partials and decides ----
    if (bid == 0) {
        long long anv = 0, acl = 0; double asl = 0.0;
        for (int i = t; i < GRID; i += NTHR) {
            anv += g_pnv[i]; acl += g_pcl[i]; asl += (double)g_psl[i];
        }
        __shared__ long long rnv[NTHR], rcl2[NTHR];
        __shared__ double rsl2[NTHR];
        rnv[t] = anv; rcl2[t] = acl; rsl2[t] = asl;
        __syncthreads();
#pragma unroll
        for (int o = NTHR / 2; o; o >>= 1) {
            if (t < o) { rnv[t] += rnv[t + o]; rcl2[t] += rcl2[t + o]; rsl2[t] += rsl2[t + o]; }
            __syncthreads();
        }
        if (t == 0) {
            long long nv = rnv[0], cl2 = rcl2[0];
            double sum = rsl2[0];
            if (nv == 0) {
                out[0] = 0.0f; g_done = 1;
            } else {
                long long k = (long long)min_kept[0];
                if (k > nv - 1) k = nv - 1;
                if (k < 0) k = 0;
                if (cl2 > k) {   // kth smallest prob < 0.7 -> threshold == 0.7; done.
                    double c = (double)cl2; if (c < 1.0) c = 1.0;
                    out[0] = (float)(sum / c);
                    g_done = 1;
                } else {
                    g_done = 0; g_krem = (int)k; g_cand_cnt = 0u;
                }
            }
        }
    }
    gbar();
    if (*(volatile int*)&g_done) return;          // fast path: all done in 1 kernel

    // ======================= slow path (exact kth select) ===================
    // phase 2: recompute probs, store g_prob; zero histogram
    for (int tid = bid * NTHR + t; tid < PIX4; tid += GRID * NTHR) {
        float pr[4], lp[4]; int tg[4];
        compute4(pred, tgt, tid, pr, lp, tg);
        *(float4*)&g_prob[tid * 4] = make_float4(pr[0], pr[1], pr[2], pr[3]);
    }
    for (int i = bid * NTHR + t; i < 65536; i += GRID * NTHR) g_hist16[i] = 0u;
    gbar();

    // phase 3: 16-bit histogram of valid prob keys
    for (int i = bid * NTHR + t; i < PIX; i += GRID * NTHR) {
        unsigned key = __float_as_uint(g_prob[i]);
        if (key < 0x40000000u)                    // valid (<2.0); sentinel 4.0 excluded
            atomicAdd(&g_hist16[key >> 16], 1u);
    }
    gbar();

    // phase 4: block 0 selects the 16-bit bin containing rank k
    if (bid == 0) {
        unsigned k = (unsigned)g_krem;
        unsigned tot = 0;
        for (int j = 0; j < 256; j++) tot += g_hist16[t * 256 + j];
        __shared__ unsigned ps[256];
        ps[t] = tot; __syncthreads();
        for (int o = 1; o < 256; o <<= 1) {
            unsigned v = (t >= o) ? ps[t - o] : 0u;
            __syncthreads();
            ps[t] += v;
            __syncthreads();
        }
        unsigned excl = ps[t] - tot;
        if (k >= excl && k < excl + tot) {
            unsigned run = excl;
            for (int j = 0; j < 256; j++) {
                unsigned c = g_hist16[t * 256 + j];
                if (k < run + c) { g_selbin = (unsigned)(t * 256 + j); g_krem2 = k - run; break; }
                run += c;
            }
        }
    }
    gbar();

    // phase 5: gather candidate keys in the selected bin
    {
        unsigned sb = g_selbin;
        for (int i = bid * NTHR + t; i < PIX; i += GRID * NTHR) {
            unsigned key = __float_as_uint(g_prob[i]);
            if ((key >> 16) == sb) {
                unsigned pos = atomicAdd(&g_cand_cnt, 1u);
                g_cand[pos] = key;
            }
        }
    }
    gbar();

    // phase 6: block 0 exact select of low 16 bits (8 + 8)
    if (bid == 0) {
        unsigned ncand = g_cand_cnt;
        __shared__ unsigned sh[256];
        __shared__ unsigned sb1, skk;
        sh[t] = 0; __syncthreads();
        for (unsigned i = t; i < ncand; i += NTHR)
            atomicAdd(&sh[(g_cand[i] >> 8) & 0xFFu], 1u);
        __syncthreads();
        if (t == 0) {
            unsigned k = g_krem2, run = 0;
            for (int j = 0; j < 256; j++) {
                unsigned c = sh[j];
                if (k < run + c) { sb1 = (unsigned)j; skk = k - run; break; }
                run += c;
            }
        }
        __syncthreads();
        unsigned b1 = sb1;
        sh[t] = 0; __syncthreads();
        for (unsigned i = t; i < ncand; i += NTHR) {
            unsigned key = g_cand[i];
            if (((key >> 8) & 0xFFu) == b1) atomicAdd(&sh[key & 0xFFu], 1u);
        }
        __syncthreads();
        if (t == 0) {
            unsigned k = skk, run = 0, b0 = 0;
            for (int j = 0; j < 256; j++) {
                unsigned c = sh[j];
                if (k < run + c) { b0 = (unsigned)j; break; }
                run += c;
            }
            unsigned key = (g_selbin << 16) | (b1 << 8) | b0;
            g_threshold = fmaxf(__uint_as_float(key), OHEM_THRESH);
        }
    }
    gbar();

    // phase 7: masked mean over hard examples
    {
        float th = g_threshold;
        float sl2 = 0.f; int cl2 = 0;
        for (int i = bid * NTHR + t; i < PIX; i += GRID * NTHR) {
            float p = g_prob[i];                  // sentinel 4.0 never < th
            if (p < th) { sl2 += -__logf(fmaxf(p, 1e-38f)); cl2++; }
        }
#pragma unroll
        for (int o = 16; o; o >>= 1) {
            sl2 += __shfl_down_sync(0xFFFFFFFFu, sl2, o);
            cl2 += __shfl_down_sync(0xFFFFFFFFu, cl2, o);
        }
        __shared__ float ssl2[8];
        __shared__ int   scl2[8];
        int w = t >> 5, l = t & 31;
        if (l == 0) { ssl2[w] = sl2; scl2[w] = cl2; }
        __syncthreads();
        if (t == 0) {
            float a3 = 0.f; int a2 = 0;
#pragma unroll
            for (int i = 0; i < 8; i++) { a3 += ssl2[i]; a2 += scl2[i]; }
            g_rsl[bid] = a3; g_rcl[bid] = a2;
        }
        __threadfence();
        __shared__ int s_last;
        if (t == 0) s_last = (atomicAdd(&g_c4, 1u) == GRID - 1);
        __syncthreads();
        if (!s_last) return;

        double asl = 0.0; long long acl2 = 0;
        for (int i = t; i < GRID; i += NTHR) { asl += (double)g_rsl[i]; acl2 += g_rcl[i]; }
        __shared__ double rs[NTHR];
        __shared__ long long rc[NTHR];
        rs[t] = asl; rc[t] = acl2;
        __syncthreads();
#pragma unroll
        for (int o = NTHR / 2; o; o >>= 1) {
            if (t < o) { rs[t] += rs[t + o]; rc[t] += rc[t + o]; }
            __syncthreads();
        }
        if (t == 0) {
            double c = (double)rc[0]; if (c < 1.0) c = 1.0;
            out[0] = (float)(rs[0] / c);
            g_c4 = 0;
        }
    }
}

// ---------------------------------------------------------------------------
extern "C" void kernel_launch(void* const* d_in, const int* in_sizes, int n_in,
                              void* d_out, int out_size) {
    const float* pred = (const float*)d_in[0];
    const int*   tgt  = (const int*)d_in[1];
    const int*   mk   = (const int*)d_in[2];
    float* out = (float*)d_out;

    k_ohem<<<GRID, NTHR>>>(pred, tgt, mk, out);   // single persistent kernel, 1 graph node
}

// round 15
// speedup vs baseline: 1.2962x; 1.0063x over previous
#include <cuda_runtime.h>
#include <cuda_bf16.h>

// Fixed shapes for this problem.
#define NIMG 8
#define NC   19
#define HW   (512 * 512)      // 262144
#define PIX  (NIMG * HW)      // 2097152
#define PIX4 (PIX / 4)        // 524288
#define GRID 444              // persistent grid: 3 CTAs/SM x 148 SMs (co-resident)
#define NTHR 256

#define OHEM_THRESH 0.7f

// ---------------- scratch (device globals; no allocation allowed) ----------
__device__ float        g_prob[PIX];       // slow path only
__device__ int          g_pnv[GRID];       // per-block valid counts
__device__ int          g_pcl[GRID];       // per-block count(prob<0.7)
__device__ float        g_psl[GRID];       // per-block sum loss(prob<0.7)
__device__ unsigned     g_hist16[65536];   // slow path: top-16-bit histogram
__device__ unsigned     g_cand[PIX];       // slow path: candidate keys in selected bin
__device__ unsigned     g_cand_cnt;
__device__ float        g_rsl[GRID];       // slow-path reduce partials
__device__ int          g_rcl[GRID];
__device__ unsigned     g_c4;              // last-block ticket (self-resetting)
__device__ int          g_done;            // 1 => fast path complete
__device__ int          g_krem;            // remaining rank
__device__ unsigned     g_selbin;          // selected 16-bit bin
__device__ unsigned     g_krem2;           // rank within selected bin
__device__ float        g_threshold;
// software global barrier (generation-based; monotone across graph replays)
__device__ unsigned     g_bar_cnt;
__device__ unsigned     g_bar_gen;

__device__ __forceinline__ void gbar() {
    __syncthreads();
    __threadfence();
    if (threadIdx.x == 0) {
        unsigned gen = *(volatile unsigned*)&g_bar_gen;
        if (atomicAdd(&g_bar_cnt, 1u) == GRID - 1) {
            g_bar_cnt = 0;
            __threadfence();
            atomicExch(&g_bar_gen, gen + 1);
        } else {
            while (*(volatile unsigned*)&g_bar_gen == gen) { __nanosleep(32); }
        }
    }
    __syncthreads();
    __threadfence();
}

// Per-pixel-group compute: 4 probs (sentinel 4.0 for ignored) and 4 log-probs.
__device__ __forceinline__ void compute4(const float* __restrict__ pred,
                                         const int* __restrict__ tgt,
                                         int tid, float pr[4], float lp[4], int tg[4]) {
    int p0 = tid * 4;
    int n  = p0 >> 18;
    int hw = p0 & (HW - 1);
    const float* base = pred + (size_t)(n * NC) * HW + hw;
    int4 t4 = *(const int4*)(tgt + p0);
    int tc0 = max(t4.x, 0), tc1 = max(t4.y, 0), tc2 = max(t4.z, 0), tc3 = max(t4.w, 0);

    float s0 = 0.f, s1 = 0.f, s2 = 0.f, s3 = 0.f;
    float xt0 = 0.f, xt1 = 0.f, xt2 = 0.f, xt3 = 0.f;
#pragma unroll
    for (int c = 0; c < NC; c++) {
        float4 v = __ldcs((const float4*)(base + (size_t)c * HW));
        s0 += __expf(v.x); s1 += __expf(v.y);
        s2 += __expf(v.z); s3 += __expf(v.w);
        if (c == tc0) xt0 = v.x;
        if (c == tc1) xt1 = v.y;
        if (c == tc2) xt2 = v.z;
        if (c == tc3) xt3 = v.w;
    }
    lp[0] = xt0 - __logf(s0); lp[1] = xt1 - __logf(s1);
    lp[2] = xt2 - __logf(s2); lp[3] = xt3 - __logf(s3);
    tg[0] = t4.x; tg[1] = t4.y; tg[2] = t4.z; tg[3] = t4.w;
#pragma unroll
    for (int j = 0; j < 4; j++) {
        float p = __expf(lp[j]);
        pr[j] = (tg[j] != -1) ? p : 4.0f;
    }
}

// =================== single persistent cooperative kernel ==================
__global__ void __launch_bounds__(NTHR, 3) k_ohem(const float* __restrict__ pred,
                                                  const int* __restrict__ tgt,
                                                  const int* __restrict__ min_kept,
                                                  float* __restrict__ out) {
    const int t = threadIdx.x;
    const int bid = blockIdx.x;

    // ---- phase 0: stream compute + speculative fast-path stats (no g_prob) ----
    int cv = 0, cl = 0; float sl = 0.f;
    for (int tid = bid * NTHR + t; tid < PIX4; tid += GRID * NTHR) {
        float pr[4], lp[4]; int tg[4];
        compute4(pred, tgt, tid, pr, lp, tg);
#pragma unroll
        for (int j = 0; j < 4; j++) {
            bool valid = (tg[j] != -1);
            cv += valid;
            bool sel = valid && (pr[j] < OHEM_THRESH);
            cl += sel;
            if (sel) sl += (-lp[j]);
        }
    }
#pragma unroll
    for (int o = 16; o; o >>= 1) {
        cv += __shfl_down_sync(0xFFFFFFFFu, cv, o);
        cl += __shfl_down_sync(0xFFFFFFFFu, cl, o);
        sl += __shfl_down_sync(0xFFFFFFFFu, sl, o);
    }
    __shared__ int scv[8], scl[8];
    __shared__ float ssl[8];
    {
        int w = t >> 5, l = t & 31;
        if (l == 0) { scv[w] = cv; scl[w] = cl; ssl[w] = sl; }
        __syncthreads();
        if (t == 0) {
            int a1 = 0, a2 = 0; float a3 = 0.f;
#pragma unroll
            for (int i = 0; i < 8; i++) { a1 += scv[i]; a2 += scl[i]; a3 += ssl[i]; }
            g_pnv[bid] = a1; g_pcl[bid] = a2; g_psl[bid] = a3;
        }
    }
    gbar();

    // ---- phase 1: block 0 reduces partials and decides ----
    if (bid == 0) {
        long long anv = 0, acl = 0; double asl = 0.0;
        for (int i = t; i < GRID; i += NTHR) {
            anv += g_pnv[i]; acl += g_pcl[i]; asl += (double)g_psl[i];
        }
        __shared__ long long rnv[NTHR], rcl2[NTHR];
        __shared__ double rsl2[NTHR];
        rnv[t] = anv; rcl2[t] = acl; rsl2[t] = asl;
        __syncthreads();
#pragma unroll
        for (int o = NTHR / 2; o; o >>= 1) {
            if (t < o) { rnv[t] += rnv[t + o]; rcl2[t] += rcl2[t + o]; rsl2[t] += rsl2[t + o]; }
            __syncthreads();
        }
        if (t == 0) {
            long long nv = rnv[0], cl2 = rcl2[0];
            double sum = rsl2[0];
            if (nv == 0) {
                out[0] = 0.0f; g_done = 1;
            } else {
                long long k = (long long)min_kept[0];
                if (k > nv - 1) k = nv - 1;
                if (k < 0) k = 0;
                if (cl2 > k) {   // kth smallest prob < 0.7 -> threshold == 0.7; done.
                    double c = (double)cl2; if (c < 1.0) c = 1.0;
                    out[0] = (float)(sum / c);
                    g_done = 1;
                } else {
                    g_done = 0; g_krem = (int)k; g_cand_cnt = 0u;
                }
            }
        }
    }
    gbar();
    if (*(volatile int*)&g_done) return;          // fast path: all done in 1 kernel

    // ======================= slow path (exact kth select) ===================
    // phase 2: recompute probs, store g_prob; zero histogram
    for (int tid = bid * NTHR + t; tid < PIX4; tid += GRID * NTHR) {
        float pr[4], lp[4]; int tg[4];
        compute4(pred, tgt, tid, pr, lp, tg);
        *(float4*)&g_prob[tid * 4] = make_float4(pr[0], pr[1], pr[2], pr[3]);
    }
    for (int i = bid * NTHR + t; i < 65536; i += GRID * NTHR) g_hist16[i] = 0u;
    gbar();

    // phase 3: 16-bit histogram of valid prob keys
    for (int i = bid * NTHR + t; i < PIX; i += GRID * NTHR) {
        unsigned key = __float_as_uint(g_prob[i]);
        if (key < 0x40000000u)                    // valid (<2.0); sentinel 4.0 excluded
            atomicAdd(&g_hist16[key >> 16], 1u);
    }
    gbar();

    // phase 4: block 0 selects the 16-bit bin containing rank k
    if (bid == 0) {
        unsigned k = (unsigned)g_krem;
        unsigned tot = 0;
        for (int j = 0; j < 256; j++) tot += g_hist16[t * 256 + j];
        __shared__ unsigned ps[256];
        ps[t] = tot; __syncthreads();
        for (int o = 1; o < 256; o <<= 1) {
            unsigned v = (t >= o) ? ps[t - o] : 0u;
            __syncthreads();
            ps[t] += v;
            __syncthreads();
        }
        unsigned excl = ps[t] - tot;
        if (k >= excl && k < excl + tot) {
            unsigned run = excl;
            for (int j = 0; j < 256; j++) {
                unsigned c = g_hist16[t * 256 + j];
                if (k < run + c) { g_selbin = (unsigned)(t * 256 + j); g_krem2 = k - run; break; }
                run += c;
            }
        }
    }
    gbar();

    // phase 5: gather candidate keys in the selected bin
    {
        unsigned sb = g_selbin;
        for (int i = bid * NTHR + t; i < PIX; i += GRID * NTHR) {
            unsigned key = __float_as_uint(g_prob[i]);
            if ((key >> 16) == sb) {
                unsigned pos = atomicAdd(&g_cand_cnt, 1u);
                g_cand[pos] = key;
            }
        }
    }
    gbar();

    // phase 6: block 0 exact select of low 16 bits (8 + 8)
    if (bid == 0) {
        unsigned ncand = g_cand_cnt;
        __shared__ unsigned sh[256];
        __shared__ unsigned sb1, skk;
        sh[t] = 0; __syncthreads();
        for (unsigned i = t; i < ncand; i += NTHR)
            atomicAdd(&sh[(g_cand[i] >> 8) & 0xFFu], 1u);
        __syncthreads();
        if (t == 0) {
            unsigned k = g_krem2, run = 0;
            for (int j = 0; j < 256; j++) {
                unsigned c = sh[j];
                if (k < run + c) { sb1 = (unsigned)j; skk = k - run; break; }
                run += c;
            }
        }
        __syncthreads();
        unsigned b1 = sb1;
        sh[t] = 0; __syncthreads();
        for (unsigned i = t; i < ncand; i += NTHR) {
            unsigned key = g_cand[i];
            if (((key >> 8) & 0xFFu) == b1) atomicAdd(&sh[key & 0xFFu], 1u);
        }
        __syncthreads();
        if (t == 0) {
            unsigned k = skk, run = 0, b0 = 0;
            for (int j = 0; j < 256; j++) {
                unsigned c = sh[j];
                if (k < run + c) { b0 = (unsigned)j; break; }
                run += c;
            }
            unsigned key = (g_selbin << 16) | (b1 << 8) | b0;
            g_threshold = fmaxf(__uint_as_float(key), OHEM_THRESH);
        }
    }
    gbar();

    // phase 7: masked mean over hard examples
    {
        float th = g_threshold;
        float sl2 = 0.f; int cl2 = 0;
        for (int i = bid * NTHR + t; i < PIX; i += GRID * NTHR) {
            float p = g_prob[i];                  // sentinel 4.0 never < th
            if (p < th) { sl2 += -__logf(fmaxf(p, 1e-38f)); cl2++; }
        }
#pragma unroll
        for (int o = 16; o; o >>= 1) {
            sl2 += __shfl_down_sync(0xFFFFFFFFu, sl2, o);
            cl2 += __shfl_down_sync(0xFFFFFFFFu, cl2, o);
        }
        __shared__ float ssl2[8];
        __shared__ int   scl2[8];
        int w = t >> 5, l = t & 31;
        if (l == 0) { ssl2[w] = sl2; scl2[w] = cl2; }
        __syncthreads();
        if (t == 0) {
            float a3 = 0.f; int a2 = 0;
#pragma unroll
            for (int i = 0; i < 8; i++) { a3 += ssl2[i]; a2 += scl2[i]; }
            g_rsl[bid] = a3; g_rcl[bid] = a2;
        }
        __threadfence();
        __shared__ int s_last;
        if (t == 0) s_last = (atomicAdd(&g_c4, 1u) == GRID - 1);
        __syncthreads();
        if (!s_last) return;

        double asl = 0.0; long long acl2 = 0;
        for (int i = t; i < GRID; i += NTHR) { asl += (double)g_rsl[i]; acl2 += g_rcl[i]; }
        __shared__ double rs[NTHR];
        __shared__ long long rc[NTHR];
        rs[t] = asl; rc[t] = acl2;
        __syncthreads();
#pragma unroll
        for (int o = NTHR / 2; o; o >>= 1) {
            if (t < o) { rs[t] += rs[t + o]; rc[t] += rc[t + o]; }
            __syncthreads();
        }
        if (t == 0) {
            double c = (double)rc[0]; if (c < 1.0) c = 1.0;
            out[0] = (float)(rs[0] / c);
            g_c4 = 0;
        }
    }
}

// ---------------------------------------------------------------------------
extern "C" void kernel_launch(void* const* d_in, const int* in_sizes, int n_in,
                              void* d_out, int out_size) {
    const float* pred = (const float*)d_in[0];
    const int*   tgt  = (const int*)d_in[1];
    const int*   mk   = (const int*)d_in[2];
    float* out = (float*)d_out;

    k_ohem<<<GRID, NTHR>>>(pred, tgt, mk, out);   // single persistent kernel, 1 graph node
}